// round 4
// baseline (speedup 1.0000x reference)
#include <cuda_runtime.h>
#include <math.h>

#define B_  2
#define S_  2048
#define D_  1024
#define H_  16
#define HD_ 64
#define EPS_ 1e-6f
#define QFOLD 0.18033688011112042f

__device__ float g_qkv[B_ * S_ * 3 * D_];
__device__ float g_o[B_ * S_ * D_];

__device__ __forceinline__ unsigned f2tf(float x) {
    unsigned r;
    asm("cvt.rna.tf32.f32 %0, %1;" : "=r"(r) : "f"(x));
    return r;
}
__device__ __forceinline__ uint4 cvt4(float4 v) {
    return make_uint4(f2tf(v.x), f2tf(v.y), f2tf(v.z), f2tf(v.w));
}
__device__ __forceinline__ void mma_tf32(float* c, const unsigned* a, const unsigned* b) {
    asm volatile(
        "mma.sync.aligned.m16n8k8.row.col.f32.tf32.tf32.f32 "
        "{%0,%1,%2,%3}, {%4,%5,%6,%7}, {%8,%9}, {%0,%1,%2,%3};"
        : "+f"(c[0]), "+f"(c[1]), "+f"(c[2]), "+f"(c[3])
        : "r"(a[0]), "r"(a[1]), "r"(a[2]), "r"(a[3]), "r"(b[0]), "r"(b[1]));
}
__device__ __forceinline__ void ldsm4(unsigned& r0, unsigned& r1, unsigned& r2,
                                      unsigned& r3, unsigned addr) {
    asm volatile("ldmatrix.sync.aligned.m8n8.x4.shared.b16 {%0,%1,%2,%3}, [%4];"
        : "=r"(r0), "=r"(r1), "=r"(r2), "=r"(r3) : "r"(addr));
}
__device__ __forceinline__ unsigned sptr(const void* p) {
    return (unsigned)__cvta_generic_to_shared(p);
}

// ---------------------------------------------------------------------------
#define AS_STR 36
#define BT_STR 36

__global__ __launch_bounds__(256, 2) void gemm_tf32_kernel(
    const float* __restrict__ A, const float* __restrict__ Bm,
    const float* __restrict__ bias, float* __restrict__ C,
    int M, int N, int K, int mode,
    const float* __restrict__ q_scale, const float* __restrict__ k_scale)
{
    __shared__ unsigned As[128 * AS_STR];
    __shared__ unsigned Bt[128 * BT_STR];

    const int tid = threadIdx.x;
    const int lane = tid & 31;
    const int wid = tid >> 5;
    const int g = lane >> 2;
    const int q = lane & 3;
    const int wm = wid >> 1;
    const int wn = wid & 1;
    const int bxn = blockIdx.x * 128;
    const int bym = blockIdx.y * 128;

    int ar[4], ac[4];
    const float* Ag[4];
#pragma unroll
    for (int i = 0; i < 4; ++i) {
        int idx = tid + 256 * i;
        ar[i] = idx >> 3; ac[i] = idx & 7;
        Ag[i] = A + (size_t)(bym + ar[i]) * K + ac[i] * 4;
    }
    const int bn = (tid & 31) + ((tid >> 6) << 5);
    const int kb = ((tid >> 5) & 1) * 16;
    const float* Bg = Bm + bxn + bn;

    unsigned a_base = sptr(As) + (((wm * 32 + (lane & 15)) * AS_STR + (lane >> 4) * 4) << 2);
    unsigned b_base = sptr(Bt) + ((((wn * 64 + (lane & 7) + ((lane >> 4) << 3))) * BT_STR
                                   + ((lane >> 3) & 1) * 4) << 2);

    float acc[2][8][4];
#pragma unroll
    for (int mf = 0; mf < 2; ++mf)
#pragma unroll
        for (int nf = 0; nf < 8; ++nf)
#pragma unroll
            for (int e = 0; e < 4; ++e) acc[mf][nf][e] = 0.f;

    const int KT = K >> 5;

    float4 av[4]; float bv[16];
#pragma unroll
    for (int i = 0; i < 4; ++i) av[i] = *(const float4*)(Ag[i]);
#pragma unroll
    for (int r = 0; r < 4; ++r)
#pragma unroll
        for (int j = 0; j < 4; ++j)
            bv[r * 4 + j] = Bg[(size_t)(kb + r * 4 + j) * N];

    for (int kt = 0; kt < KT; ++kt) {
        __syncthreads();
#pragma unroll
        for (int i = 0; i < 4; ++i)
            *(uint4*)&As[ar[i] * AS_STR + ac[i] * 4] = cvt4(av[i]);
#pragma unroll
        for (int r = 0; r < 4; ++r) {
            uint4 t = make_uint4(f2tf(bv[r * 4]), f2tf(bv[r * 4 + 1]),
                                 f2tf(bv[r * 4 + 2]), f2tf(bv[r * 4 + 3]));
            *(uint4*)&Bt[bn * BT_STR + kb + r * 4] = t;
        }
        __syncthreads();

        if (kt + 1 < KT) {
            const int k0 = (kt + 1) * 32;
#pragma unroll
            for (int i = 0; i < 4; ++i) av[i] = *(const float4*)(Ag[i] + k0);
#pragma unroll
            for (int r = 0; r < 4; ++r)
#pragma unroll
                for (int j = 0; j < 4; ++j)
                    bv[r * 4 + j] = Bg[(size_t)(k0 + kb + r * 4 + j) * N];
        }

#pragma unroll
        for (int kk = 0; kk < 4; ++kk) {
            unsigned a0[4], a1[4], bl[4][4];
            ldsm4(a0[0], a0[1], a0[2], a0[3], a_base + kk * 32);
            ldsm4(a1[0], a1[1], a1[2], a1[3], a_base + 16 * AS_STR * 4 + kk * 32);
#pragma unroll
            for (int t2 = 0; t2 < 4; ++t2)
                ldsm4(bl[t2][0], bl[t2][1], bl[t2][2], bl[t2][3],
                      b_base + t2 * 16 * BT_STR * 4 + kk * 32);
#pragma unroll
            for (int nf = 0; nf < 8; ++nf) {
                const unsigned* bf = &bl[nf >> 1][(nf & 1) * 2];
                mma_tf32(acc[0][nf], a0, bf);
                mma_tf32(acc[1][nf], a1, bf);
            }
        }
    }

    const bool donorm = (mode == 1) && (bxn < 2048);
    const float* sc = (bxn < 1024) ? q_scale : k_scale;
    const float fold = (bxn < 1024) ? QFOLD : 1.0f;

#pragma unroll
    for (int mf = 0; mf < 2; ++mf) {
        int r0 = bym + wm * 32 + mf * 16 + g;
#pragma unroll
        for (int nf = 0; nf < 8; ++nf) {
            int col = bxn + wn * 64 + nf * 8 + 2 * q;
            float2 bs = *(const float2*)(bias + col);
            acc[mf][nf][0] += bs.x; acc[mf][nf][1] += bs.y;
            acc[mf][nf][2] += bs.x; acc[mf][nf][3] += bs.y;
        }
        if (donorm) {
#pragma unroll
            for (int rh = 0; rh < 2; ++rh) {
                const int e0 = rh * 2, e1 = e0 + 1;
                float ss = 0.f;
#pragma unroll
                for (int nf = 0; nf < 8; ++nf)
                    ss += acc[mf][nf][e0] * acc[mf][nf][e0]
                        + acc[mf][nf][e1] * acc[mf][nf][e1];
                ss += __shfl_xor_sync(0xffffffffu, ss, 1);
                ss += __shfl_xor_sync(0xffffffffu, ss, 2);
                float rr = rsqrtf(ss * (1.0f / HD_) + EPS_) * fold;
#pragma unroll
                for (int nf = 0; nf < 8; ++nf) {
                    float2 s2 = *(const float2*)(sc + nf * 8 + 2 * q);
                    acc[mf][nf][e0] *= rr * s2.x;
                    acc[mf][nf][e1] *= rr * s2.y;
                }
            }
        }
#pragma unroll
        for (int nf = 0; nf < 8; ++nf) {
            int col = bxn + wn * 64 + nf * 8 + 2 * q;
            *(float2*)(C + (size_t)r0 * N + col) =
                make_float2(acc[mf][nf][0], acc[mf][nf][1]);
            *(float2*)(C + (size_t)(r0 + 8) * N + col) =
                make_float2(acc[mf][nf][2], acc[mf][nf][3]);
        }
    }
}

// ---------------------------------------------------------------------------
#define TS 68
#define OFF_K  (128 * TS)
#define OFF_V  (OFF_K + 64 * TS)
#define OFF_P  (OFF_V + 64 * TS)
#define ATT_SMEM ((OFF_P + 128 * TS) * 4)

__global__ __launch_bounds__(256, 2) void attn_tf32_kernel(
    const float* __restrict__ qkv, float* __restrict__ o)
{
    extern __shared__ unsigned sm[];
    unsigned* Qs = sm;
    unsigned* Ks = sm + OFF_K;
    unsigned* Vt = sm + OFF_V;
    unsigned* Ps = sm + OFF_P;

    const int tid = threadIdx.x;
    const int lane = tid & 31;
    const int w = tid >> 5;
    const int g = lane >> 2;
    const int q = lane & 3;
    const int q0 = blockIdx.x * 128;
    const int bh = blockIdx.y;
    const int b = bh >> 4;
    const int h = bh & 15;

    const float* base = qkv + (size_t)b * S_ * 3 * D_ + h * HD_;

#pragma unroll
    for (int i = 0; i < 8; ++i) {
        int idx = tid + 256 * i;
        int r = idx >> 4, c = idx & 15;
        float4 v4 = *(const float4*)(base + (size_t)(q0 + r) * (3 * D_) + c * 4);
        *(uint4*)&Qs[r * TS + c * 4] = cvt4(v4);
    }

    const int vhd = (tid & 31) + ((tid >> 5) & 1) * 32;
    const int vk0 = (tid >> 6) * 16;

    unsigned qbase = sptr(Qs) + (((w * 16 + (lane & 15)) * TS + (lane >> 4) * 4) << 2);
    unsigned pbase = sptr(Ps) + (((w * 16 + (lane & 15)) * TS + (lane >> 4) * 4) << 2);
    const unsigned brow = (((lane & 7) + ((lane >> 4) << 3)) * TS + ((lane >> 3) & 1) * 4) << 2;
    unsigned kbase = sptr(Ks) + brow;
    unsigned vbase = sptr(Vt) + brow;

    float mst[2] = {-1e30f, -1e30f}, lst[2] = {0.f, 0.f};
    float acco[8][4];
#pragma unroll
    for (int nf = 0; nf < 8; ++nf)
#pragma unroll
        for (int e = 0; e < 4; ++e) acco[nf][e] = 0.f;

    // prologue: K/V tile 0 into registers
    float4 kv4[4]; float vv[16];
#pragma unroll
    for (int i = 0; i < 4; ++i) {
        int idx = tid + 256 * i;
        int r = idx >> 4, c = idx & 15;
        kv4[i] = *(const float4*)(base + (size_t)r * (3 * D_) + D_ + c * 4);
    }
    {
        const float* vp = base + (size_t)vk0 * (3 * D_) + 2 * D_ + vhd;
#pragma unroll
        for (int j = 0; j < 16; ++j) vv[j] = vp[(size_t)j * (3 * D_)];
    }

    for (int kv0 = 0; kv0 < S_; kv0 += 64) {
        __syncthreads();
#pragma unroll
        for (int i = 0; i < 4; ++i) {
            int idx = tid + 256 * i;
            int r = idx >> 4, c = idx & 15;
            *(uint4*)&Ks[r * TS + c * 4] = cvt4(kv4[i]);
        }
#pragma unroll
        for (int rep = 0; rep < 4; ++rep) {
            uint4 t = make_uint4(f2tf(vv[rep * 4]), f2tf(vv[rep * 4 + 1]),
                                 f2tf(vv[rep * 4 + 2]), f2tf(vv[rep * 4 + 3]));
            *(uint4*)&Vt[vhd * TS + vk0 + rep * 4] = t;
        }
        __syncthreads();

        if (kv0 + 64 < S_) {
            const float* nbase = base + (size_t)(kv0 + 64) * (3 * D_);
#pragma unroll
            for (int i = 0; i < 4; ++i) {
                int idx = tid + 256 * i;
                int r = idx >> 4, c = idx & 15;
                kv4[i] = *(const float4*)(nbase + (size_t)r * (3 * D_) + D_ + c * 4);
            }
            const float* vp = nbase + (size_t)vk0 * (3 * D_) + 2 * D_ + vhd;
#pragma unroll
            for (int j = 0; j < 16; ++j) vv[j] = vp[(size_t)j * (3 * D_)];
        }

        float accs[8][4];
#pragma unroll
        for (int nf = 0; nf < 8; ++nf)
#pragma unroll
            for (int e = 0; e < 4; ++e) accs[nf][e] = 0.f;
#pragma unroll
        for (int ks = 0; ks < 8; ++ks) {
            unsigned a[4], bl[4][4];
            ldsm4(a[0], a[1], a[2], a[3], qbase + ks * 32);
#pragma unroll
            for (int t2 = 0; t2 < 4; ++t2)
                ldsm4(bl[t2][0], bl[t2][1], bl[t2][2], bl[t2][3],
                      kbase + t2 * 16 * TS * 4 + ks * 32);
#pragma unroll
            for (int nf = 0; nf < 8; ++nf)
                mma_tf32(accs[nf], a, &bl[nf >> 1][(nf & 1) * 2]);
        }

#pragma unroll
        for (int rh = 0; rh < 2; ++rh) {
            const int e0 = rh * 2, e1 = e0 + 1;
            float mold = mst[rh];
            float mx = mold;
#pragma unroll
            for (int nf = 0; nf < 8; ++nf)
                mx = fmaxf(mx, fmaxf(accs[nf][e0], accs[nf][e1]));
            mx = fmaxf(mx, __shfl_xor_sync(0xffffffffu, mx, 1));
            mx = fmaxf(mx, __shfl_xor_sync(0xffffffffu, mx, 2));
            float corr = exp2f(mold - mx);
            mst[rh] = mx;
            float sum = 0.f;
            int rowb = (w * 16 + g + rh * 8) * TS + 2 * q;
#pragma unroll
            for (int nf = 0; nf < 8; ++nf) {
                float p0 = exp2f(accs[nf][e0] - mx);
                float p1 = exp2f(accs[nf][e1] - mx);
                sum += p0 + p1;
                *(uint2*)&Ps[rowb + nf * 8] = make_uint2(f2tf(p0), f2tf(p1));
                acco[nf][e0] *= corr;
                acco[nf][e1] *= corr;
            }
            sum += __shfl_xor_sync(0xffffffffu, sum, 1);
            sum += __shfl_xor_sync(0xffffffffu, sum, 2);
            lst[rh] = lst[rh] * corr + sum;
        }
        __syncwarp();

#pragma unroll
        for (int ks = 0; ks < 8; ++ks) {
            unsigned a[4], bl[4][4];
            ldsm4(a[0], a[1], a[2], a[3], pbase + ks * 32);
#pragma unroll
            for (int t2 = 0; t2 < 4; ++t2)
                ldsm4(bl[t2][0], bl[t2][1], bl[t2][2], bl[t2][3],
                      vbase + t2 * 16 * TS * 4 + ks * 32);
#pragma unroll
            for (int nf = 0; nf < 8; ++nf)
                mma_tf32(acco[nf], a, &bl[nf >> 1][(nf & 1) * 2]);
        }
    }

#pragma unroll
    for (int rh = 0; rh < 2; ++rh) {
        float inv = 1.0f / lst[rh];
        int row = q0 + w * 16 + g + rh * 8;
        float* orow = o + (size_t)(b * S_ + row) * D_ + h * HD_;
        const int e0 = rh * 2, e1 = e0 + 1;
#pragma unroll
        for (int nf = 0; nf < 8; ++nf)
            *(float2*)(orow + nf * 8 + 2 * q) =
                make_float2(acco[nf][e0] * inv, acco[nf][e1] * inv);
    }
}

// ---------------------------------------------------------------------------
extern "C" void kernel_launch(void* const* d_in, const int* in_sizes, int n_in,
                              void* d_out, int out_size)
{
    const float* x       = (const float*)d_in[0];
    const float* Wqkv    = (const float*)d_in[1];
    const float* bqkv    = (const float*)d_in[2];
    const float* Wout    = (const float*)d_in[3];
    const float* bout    = (const float*)d_in[4];
    const float* q_scale = (const float*)d_in[5];
    const float* k_scale = (const float*)d_in[6];
    float* out = (float*)d_out;

    float* qkv; cudaGetSymbolAddress((void**)&qkv, g_qkv);
    float* o;   cudaGetSymbolAddress((void**)&o,   g_o);

    {
        dim3 grid(3 * D_ / 128, (B_ * S_) / 128);
        gemm_tf32_kernel<<<grid, 256>>>(x, Wqkv, bqkv, qkv, B_ * S_, 3 * D_, D_,
                                        1, q_scale, k_scale);
    }
    {
        cudaFuncSetAttribute((const void*)attn_tf32_kernel,
                             cudaFuncAttributeMaxDynamicSharedMemorySize, ATT_SMEM);
        dim3 grid(S_ / 128, B_ * H_);
        attn_tf32_kernel<<<grid, 256, ATT_SMEM>>>(qkv, o);
    }
    {
        dim3 grid(D_ / 128, (B_ * S_) / 128);
        gemm_tf32_kernel<<<grid, 256>>>(o, Wout, bout, out, B_ * S_, D_, D_,
                                        0, q_scale, k_scale);
    }
}